// round 10
// baseline (speedup 1.0000x reference)
#include <cuda_runtime.h>
#include <cuda_bf16.h>

// Inputs (metadata order):
//   d_in[0] : energy_readout            float32 [262144]
//   d_in[1] : atomic_numbers            int32   [8388608]
//   d_in[2] : atomic_subsystem_indices  int32   [8388608]  (sorted ascending)
//   d_in[3] : self_energies_tensor      float32 [100]
// Output: float32 [262144] = energy_readout + segment_sum(se[Z], seg_idx)

#define LUT_SIZE_MAX 128
#define CHUNK 8           // atoms per thread per iteration
#define TPB 256
#define GRID_SEGSUM 1024  // 2^18 threads; 2^20 chunks -> exactly 4 iters/thread

__global__ void init_out_kernel(const float* __restrict__ e,
                                float* __restrict__ out, int n4) {
    int i = blockIdx.x * blockDim.x + threadIdx.x;
    if (i < n4) {
        reinterpret_cast<float4*>(out)[i] =
            reinterpret_cast<const float4*>(e)[i];
    }
}

__device__ __forceinline__ void process_chunk(const int4& zv0, const int4& zv1,
                                              const int4& sv0, const int4& sv1,
                                              const float* __restrict__ s_se,
                                              float* __restrict__ out) {
    int   s[8] = {sv0.x, sv0.y, sv0.z, sv0.w, sv1.x, sv1.y, sv1.z, sv1.w};
    int   z[8] = {zv0.x, zv0.y, zv0.z, zv0.w, zv1.x, zv1.y, zv1.z, zv1.w};
    int cur_seg = s[0];
    float run_sum = 0.0f;
#pragma unroll
    for (int k = 0; k < 8; k++) {
        if (s[k] != cur_seg) {
            atomicAdd(out + cur_seg, run_sum);
            cur_seg = s[k];
            run_sum = 0.0f;
        }
        run_sum += s_se[z[k]];
    }
    atomicAdd(out + cur_seg, run_sum);
}

__global__ void __launch_bounds__(TPB)
self_energy_segsum_kernel(const int* __restrict__ zs,
                          const int* __restrict__ seg,
                          const float* __restrict__ se,
                          float* __restrict__ out,
                          int n_atoms, int n_se) {
    __shared__ float s_se[LUT_SIZE_MAX];
    for (int i = threadIdx.x; i < LUT_SIZE_MAX; i += blockDim.x)
        s_se[i] = (i < n_se) ? se[i] : 0.0f;
    __syncthreads();

    const int tid = blockIdx.x * TPB + threadIdx.x;
    const int total_threads = gridDim.x * TPB;
    const int n_chunks = n_atoms / CHUNK;

    // Software-pipelined grid-stride: iteration k+1's global loads are issued
    // BEFORE iteration k's epilogue, so each warp keeps ~4 cache lines in
    // flight even while doing LDS gathers / branches / atomics.
    int c = tid;
    bool valid = (c < n_chunks);
    int4 zv0, zv1, sv0, sv1;
    if (valid) {
        long long base = (long long)c * CHUNK;
        const int4* z4 = reinterpret_cast<const int4*>(zs + base);
        const int4* s4 = reinterpret_cast<const int4*>(seg + base);
        zv0 = z4[0]; zv1 = z4[1]; sv0 = s4[0]; sv1 = s4[1];
    }

    while (valid) {
        int cn = c + total_threads;
        bool nvalid = (cn < n_chunks);
        int4 nz0, nz1, ns0, ns1;
        if (nvalid) {  // prefetch next chunk first
            long long nbase = (long long)cn * CHUNK;
            const int4* z4 = reinterpret_cast<const int4*>(zs + nbase);
            const int4* s4 = reinterpret_cast<const int4*>(seg + nbase);
            nz0 = z4[0]; nz1 = z4[1]; ns0 = s4[0]; ns1 = s4[1];
        }

        process_chunk(zv0, zv1, sv0, sv1, s_se, out);

        zv0 = nz0; zv1 = nz1; sv0 = ns0; sv1 = ns1;
        c = cn; valid = nvalid;
    }

    // Tail atoms not covered by full chunks (none for 8388608, but be general)
    int tail_start = n_chunks * CHUNK;
    if (tid == 0 && tail_start < n_atoms) {
        int cs = -1; float rs = 0.0f;
        for (int i = tail_start; i < n_atoms; i++) {
            int s = seg[i];
            if (s != cs) { if (cs >= 0) atomicAdd(out + cs, rs); cs = s; rs = 0.0f; }
            rs += s_se[zs[i]];
        }
        if (cs >= 0) atomicAdd(out + cs, rs);
    }
}

extern "C" void kernel_launch(void* const* d_in, const int* in_sizes, int n_in,
                              void* d_out, int out_size) {
    const float* energy = (const float*)d_in[0];
    const int*   zs     = (const int*)d_in[1];
    const int*   seg    = (const int*)d_in[2];
    const float* se     = (const float*)d_in[3];
    float* out = (float*)d_out;

    int n_mol   = in_sizes[0];
    int n_atoms = in_sizes[1];
    int n_se    = in_sizes[3];

    // 1) out = energy_readout (d_out comes in poisoned). n_mol is 4-aligned.
    {
        int n4 = n_mol / 4;
        int blocks = (n4 + TPB - 1) / TPB;
        init_out_kernel<<<blocks, TPB>>>(energy, out, n4);
    }

    // 2) pipelined segment sum with run-compressed atomics
    self_energy_segsum_kernel<<<GRID_SEGSUM, TPB>>>(zs, seg, se, out, n_atoms, n_se);
}